// round 6
// baseline (speedup 1.0000x reference)
#include <cuda_runtime.h>
#include <cstdint>

// LTC MemoryCell: B=32, T=128, d=128, units=256, ODE_UNFOLDS=6.
// Each (v[b,j], v[b,j+d]) pair is an independent 2-dim recurrence; one thread
// per (b,j), all params in registers.
//
// R5 (resubmit after infra timeout): R3 was MUFU-port-bound: 4x tanh.f32
// (rt~16) + 2x rcp (rt~8) = ~80 cyc. Pack the 4 tanh into 2x
// tanh.approx.f16x2 (args paired per target), with f32 pack/unpack on the
// fixed pipe. MUFU port drops to ~48; chain ~54.

#define Dn      128
#define UNITS   256
#define Tn      128
#define UNFOLDS 6
#define EPSc    1e-8f

__device__ __forceinline__ float tanhf_(float x) {
    float y; asm("tanh.approx.f32 %0, %1;" : "=f"(y) : "f"(x)); return y;
}
__device__ __forceinline__ float rcpf(float x) {
    float y; asm("rcp.approx.ftz.f32 %0, %1;" : "=f"(y) : "f"(x)); return y;
}
__device__ __forceinline__ uint32_t pack_h2(float hi, float lo) {
    uint32_t r; asm("cvt.rn.f16x2.f32 %0, %1, %2;" : "=r"(r) : "f"(hi), "f"(lo));
    return r;
}
__device__ __forceinline__ uint32_t tanh_h2(uint32_t x) {
    uint32_t y; asm("tanh.approx.f16x2 %0, %1;" : "=r"(y) : "r"(x));
    return y;
}
__device__ __forceinline__ float h2_lo(uint32_t h2) {
    float f;
    asm("{ .reg .f16 l, h; mov.b32 {l, h}, %1; cvt.f32.f16 %0, l; }"
        : "=f"(f) : "r"(h2));
    return f;
}
__device__ __forceinline__ float h2_hi(uint32_t h2) {
    float f;
    asm("{ .reg .f16 l, h; mov.b32 {l, h}, %1; cvt.f32.f16 %0, h; }"
        : "=f"(f) : "r"(h2));
    return f;
}

__global__ void __launch_bounds__(Dn, 1) ltc_kernel(
    const float* __restrict__ X,       // (B,T,d)
    const float* __restrict__ in_w,    // (d)
    const float* __restrict__ in_b,    // (d)
    const float* __restrict__ out_w,   // (d)
    const float* __restrict__ out_b,   // (d)
    const float* __restrict__ gleak,   // (units)
    const float* __restrict__ vleak,   // (units)
    const float* __restrict__ cm,      // (units)
    const float* __restrict__ w,       // (units,units)
    const float* __restrict__ mu,      // (units,units)
    const float* __restrict__ sigma,   // (units,units)
    const float* __restrict__ erev,    // (units,units)
    const float* __restrict__ sw,      // (d,units)
    const float* __restrict__ smu,     // (d,units)
    const float* __restrict__ ssig,    // (d,units)
    const float* __restrict__ serev,   // (d,units)
    float* __restrict__ out)           // (B,d)
{
    const int j  = threadIdx.x;        // pair index, 0..d-1
    const int b  = blockIdx.x;         // batch index
    const int jc = j + Dn;             // partner unit

    // synapse flat indices (row-major (src, tgt))
    const int i_aa = j  * UNITS + j;   // j   -> j
    const int i_ca = jc * UNITS + j;   // j+d -> j
    const int i_cc = jc * UNITS + jc;  // j+d -> j+d
    const int i_ac = j  * UNITS + jc;  // j   -> j+d

    // sigmoid((v-mu)*sig) = 0.5 + 0.5*tanh(0.5*sig*v - 0.5*sig*mu)
    float sg, m;
    sg = __ldg(sigma + i_aa); m = __ldg(mu + i_aa);
    const float c1_aa = 0.5f * sg, c0_aa = -0.5f * sg * m;
    sg = __ldg(sigma + i_ca); m = __ldg(mu + i_ca);
    const float c1_ca = 0.5f * sg, c0_ca = -0.5f * sg * m;
    sg = __ldg(sigma + i_cc); m = __ldg(mu + i_cc);
    const float c1_cc = 0.5f * sg, c0_cc = -0.5f * sg * m;
    sg = __ldg(sigma + i_ac); m = __ldg(mu + i_ac);
    const float c1_ac = 0.5f * sg, c0_ac = -0.5f * sg * m;

    // w*sigmoid = 0.5*w + (0.5*w)*tanh ; same for w*erev
    const float w2_aa = 0.5f * __ldg(w + i_aa), we2_aa = w2_aa * __ldg(erev + i_aa);
    const float w2_ca = 0.5f * __ldg(w + i_ca), we2_ca = w2_ca * __ldg(erev + i_ca);
    const float w2_cc = 0.5f * __ldg(w + i_cc), we2_cc = w2_cc * __ldg(erev + i_cc);
    const float w2_ac = 0.5f * __ldg(w + i_ac), we2_ac = w2_ac * __ldg(erev + i_ac);

    // sensory synapses: src j -> tgt j (A) and src j -> tgt j+d (C)
    const int is_a = j * UNITS + j;
    const int is_c = j * UNITS + jc;
    sg = __ldg(ssig + is_a); m = __ldg(smu + is_a);
    const float sc1A = 0.5f * sg, sc0A = -0.5f * sg * m;
    sg = __ldg(ssig + is_c); m = __ldg(smu + is_c);
    const float sc1C = 0.5f * sg, sc0C = -0.5f * sg * m;
    const float sw2A = 0.5f * __ldg(sw + is_a), ser2A = sw2A * __ldg(serev + is_a);
    const float sw2C = 0.5f * __ldg(sw + is_c), ser2C = sw2C * __ldg(serev + is_c);

    // per-unit params
    const float glA = __ldg(gleak + j),  glC = __ldg(gleak + jc);
    const float vlA = __ldg(vleak + j),  vlC = __ldg(vleak + jc);
    const float cmtA = __ldg(cm + j)  * (float)UNFOLDS;
    const float cmtC = __ldg(cm + jc) * (float)UNFOLDS;

    // static parts of num/den bases (tanh half-weights folded in; EPS in den)
    const float numBaseA = fmaf(glA, vlA, we2_aa + we2_ca) + ser2A;
    const float numBaseC = fmaf(glC, vlC, we2_cc + we2_ac) + ser2C;
    const float denBaseA = cmtA + glA + w2_aa + w2_ca + EPSc + sw2A;
    const float denBaseC = cmtC + glC + w2_cc + w2_ac + EPSc + sw2C;

    const float inw = __ldg(in_w + j), inb = __ldg(in_b + j);
    const float ow  = __ldg(out_w + j), ob = __ldg(out_b + j);

    const float* xp = X + ((size_t)b * Tn) * Dn + j;

    // carry (num, D) with v = num * rcp(D); v0 = 0
    float numA = 0.0f, DA = 1.0f;
    float numC = 0.0f, DC = 1.0f;

    // ---- software-pipelined sensory state (f32 tanh: off critical path) ----
    float xt0 = fmaf(__ldg(xp), inw, inb);
    float ths;
    ths = tanhf_(fmaf(sc1A, xt0, sc0A));
    float nbA = fmaf(ser2A, ths, numBaseA);
    float dbA = fmaf(sw2A,  ths, denBaseA);
    ths = tanhf_(fmaf(sc1C, xt0, sc0C));
    float nbC = fmaf(ser2C, ths, numBaseC);
    float dbC = fmaf(sw2C,  ths, denBaseC);

    float xnext = __ldg(xp + Dn);        // raw x for t=1

    #pragma unroll 2
    for (int t = 0; t < Tn; ++t) {
        // ---- NEXT timestep's sensory bases (independent of v) ----
        const float xtn = fmaf(xnext, inw, inb);
        const float thsA_n = tanhf_(fmaf(sc1A, xtn, sc0A));
        const float thsC_n = tanhf_(fmaf(sc1C, xtn, sc0C));
        const float nbA_n = fmaf(ser2A, thsA_n, numBaseA);
        const float dbA_n = fmaf(sw2A,  thsA_n, denBaseA);
        const float nbC_n = fmaf(ser2C, thsC_n, numBaseC);
        const float dbC_n = fmaf(sw2C,  thsC_n, denBaseC);
        {   // branchless prefetch of x for t+2
            const int tnn = (t + 2 < Tn) ? (t + 2) : (Tn - 1);
            xnext = __ldg(xp + tnn * Dn);
        }

        #pragma unroll
        for (int u = 0; u < UNFOLDS; ++u) {
            const float rdA = rcpf(DA);
            const float rdC = rcpf(DC);
            // multipliers computed in the rcp shadow (depend only on num)
            const float pAA = c1_aa * numA;
            const float pAC = c1_ac * numA;
            const float pmA = cmtA * numA;
            const float pCA = c1_ca * numC;
            const float pCC = c1_cc * numC;
            const float pmC = cmtC * numC;

            const float zAA = fmaf(pAA, rdA, c0_aa);
            const float zCA = fmaf(pCA, rdC, c0_ca);
            const float zCC = fmaf(pCC, rdC, c0_cc);
            const float zAC = fmaf(pAC, rdA, c0_ac);

            // two f16x2 tanh cover all four synapses (paired per target)
            const uint32_t hA = tanh_h2(pack_h2(zAA, zCA));  // hi=AA, lo=CA
            const uint32_t hC = tanh_h2(pack_h2(zCC, zAC));  // hi=CC, lo=AC

            const float thAA = h2_hi(hA);
            const float thCA = h2_lo(hA);
            const float thCC = h2_hi(hC);
            const float thAC = h2_lo(hC);

            // early partial sums (ready before tanh results)
            const float snA = fmaf(pmA, rdA, nbA);
            const float snC = fmaf(pmC, rdC, nbC);

            float nA = fmaf(we2_aa, thAA, snA);
            nA = fmaf(we2_ca, thCA, nA);
            float dA = fmaf(w2_aa, thAA, dbA);
            dA = fmaf(w2_ca, thCA, dA);

            float nC = fmaf(we2_cc, thCC, snC);
            nC = fmaf(we2_ac, thAC, nC);
            float dC = fmaf(w2_cc, thCC, dbC);
            dC = fmaf(w2_ac, thAC, dC);

            numA = nA; DA = dA;
            numC = nC; DC = dC;
        }

        // rotate pipelined sensory state
        nbA = nbA_n; dbA = dbA_n;
        nbC = nbC_n; dbC = dbC_n;
    }

    const float vA = numA * rcpf(DA);
    out[b * Dn + j] = fmaf(vA, ow, ob);
}

extern "C" void kernel_launch(void* const* d_in, const int* in_sizes, int n_in,
                              void* d_out, int out_size) {
    const float* X     = (const float*)d_in[0];
    const float* in_w  = (const float*)d_in[1];
    const float* in_b  = (const float*)d_in[2];
    const float* out_w = (const float*)d_in[3];
    const float* out_b = (const float*)d_in[4];
    const float* gleak = (const float*)d_in[5];
    const float* vleak = (const float*)d_in[6];
    const float* cmp   = (const float*)d_in[7];
    const float* w     = (const float*)d_in[8];
    const float* mu    = (const float*)d_in[9];
    const float* sigma = (const float*)d_in[10];
    const float* erev  = (const float*)d_in[11];
    const float* sw    = (const float*)d_in[12];
    const float* smu   = (const float*)d_in[13];
    const float* ssig  = (const float*)d_in[14];
    const float* serev = (const float*)d_in[15];
    float* out = (float*)d_out;

    const int B = in_sizes[0] / (Tn * Dn);   // 32
    ltc_kernel<<<B, Dn>>>(X, in_w, in_b, out_w, out_b,
                          gleak, vleak, cmp, w, mu, sigma, erev,
                          sw, smu, ssig, serev, out);
}